// round 16
// baseline (speedup 1.0000x reference)
#include <cuda_runtime.h>
#include <cuda_fp16.h>
#include <math.h>
#include <stdint.h>

#define NN 100000
#define PADN 100096   // 782 * 128
#define EE 300000
#define CH 256
#define LL 8
#define NCLS 40
#define SCAN_BS 1024
#define SCAN_NB 98   // ceil(100000/1024)

// ---------------- helpers ----------------
__device__ __forceinline__ uint32_t smem_u32(const void* p) {
    uint32_t a;
    asm("{ .reg .u64 t; cvta.to.shared.u64 t, %1; cvt.u32.u64 %0, t; }" : "=r"(a) : "l"(p));
    return a;
}
__device__ __forceinline__ void ldsm_x4(uint32_t* r, uint32_t addr) {
    asm volatile("ldmatrix.sync.aligned.m8n8.x4.shared.b16 {%0,%1,%2,%3}, [%4];"
                 : "=r"(r[0]), "=r"(r[1]), "=r"(r[2]), "=r"(r[3]) : "r"(addr));
}
__device__ __forceinline__ void mma16816h(float* d, const uint32_t* a, uint32_t b0, uint32_t b1) {
    asm volatile(
        "mma.sync.aligned.m16n8k16.row.col.f32.f16.f16.f32 "
        "{%0,%1,%2,%3}, {%4,%5,%6,%7}, {%8,%9}, {%0,%1,%2,%3};"
        : "+f"(d[0]), "+f"(d[1]), "+f"(d[2]), "+f"(d[3])
        : "r"(a[0]), "r"(a[1]), "r"(a[2]), "r"(a[3]), "r"(b0), "r"(b1));
}
#define CP16(dst, src) \
    asm volatile("cp.async.cg.shared.global [%0], [%1], 16;" :: "r"(dst), "l"(src))
#define CP_COMMIT() asm volatile("cp.async.commit_group;" ::: "memory")
#define CP_WAIT(n)  asm volatile("cp.async.wait_group %0;" :: "n"(n) : "memory")

__device__ __forceinline__ uint32_t packh2(float a, float b) {
    __half2 h = __floats2half2_rn(a, b);
    return *(uint32_t*)&h;
}
__device__ __forceinline__ float2 unpackh2(uint32_t u) {
    return __half22float2(*(__half2*)&u);
}

// ---------------- device scratch ----------------
__device__ __half g_h0[(size_t)PADN * CH];          // fp16 h0
__device__ __half g_h [(size_t)PADN * CH];          // fp16 h
__device__ __half g_x [(size_t)PADN * CH];          // fp16 x plane (zero-padded tail)
__device__ __half g_Bw [(size_t)LL * 256 * 256];    // gcn eff weights [l][n][k], fp16
__device__ __half g_BLw[(size_t)2 * 128 * 256];     // lin weights [v][n][k], fp16
__device__ int   g_deg[NN];
__device__ int   g_rs [NN];
__device__ int   g_cur[NN];
__device__ int   g_incl[NN];
__device__ int   g_bsum[SCAN_NB];
__device__ int   g_boff[SCAN_NB];
__device__ int   g_csrc[EE];

// ---------------- weight prep ----------------
__global__ void k_prep_gcn(const float* __restrict__ gcn_w) {
    int idx = blockIdx.x * blockDim.x + threadIdx.x;
    if (idx >= LL * 256 * 256) return;
    int l = idx >> 16;
    int n = (idx >> 8) & 255;
    int k = idx & 255;
    float beta = logf(0.5f / (float)(l + 1) + 1.0f);
    float w = gcn_w[l * 65536 + k * 256 + n];
    float eff = beta * w + ((n == k) ? (1.0f - beta) : 0.0f);
    g_Bw[idx] = __float2half_rn(eff);
}
__global__ void k_prep_lin(const float* __restrict__ lin_w) {
    int idx = blockIdx.x * blockDim.x + threadIdx.x;
    if (idx >= 2 * 128 * 256) return;
    int v = idx >> 15;
    int n = (idx >> 8) & 127;
    int k = idx & 255;
    g_BLw[idx] = __float2half_rn(lin_w[v * 32768 + k * 128 + n]);
}

// ---------------- CSR build ----------------
__global__ void k_zero_deg() {
    int i = blockIdx.x * blockDim.x + threadIdx.x;
    if (i < NN) g_deg[i] = 0;
}
__global__ void k_hist(const int* __restrict__ dst) {
    int e = blockIdx.x * blockDim.x + threadIdx.x;
    if (e < EE) atomicAdd(&g_deg[dst[e]], 1);
}
__global__ void k_scan1() {
    __shared__ int sm[SCAN_BS];
    int tid = threadIdx.x;
    int i = blockIdx.x * SCAN_BS + tid;
    int v = (i < NN) ? g_deg[i] : 0;
    sm[tid] = v;
    __syncthreads();
    for (int off = 1; off < SCAN_BS; off <<= 1) {
        int t = (tid >= off) ? sm[tid - off] : 0;
        __syncthreads();
        sm[tid] += t;
        __syncthreads();
    }
    if (i < NN) g_incl[i] = sm[tid];
    if (tid == SCAN_BS - 1) g_bsum[blockIdx.x] = sm[tid];
}
__global__ void k_scan2() {
    if (threadIdx.x == 0) {
        int s = 0;
        for (int b = 0; b < SCAN_NB; b++) { g_boff[b] = s; s += g_bsum[b]; }
    }
}
__global__ void k_scan3() {
    int i = blockIdx.x * blockDim.x + threadIdx.x;
    if (i >= NN) return;
    int rs = g_boff[i >> 10] + g_incl[i] - g_deg[i];
    g_rs[i] = rs;
    g_cur[i] = rs;
}
__global__ void k_scatter(const int* __restrict__ src, const int* __restrict__ dst) {
    int e = blockIdx.x * blockDim.x + threadIdx.x;
    if (e >= EE) return;
    int p = atomicAdd(&g_cur[dst[e]], 1);
    g_csrc[p] = src[e];
}

// ---- aggregation: x = fp16(0.9*sum h[src] + 0.1*h0) ----
__global__ void k_agg() {
    int node = blockIdx.x * blockDim.y + threadIdx.y;
    if (node >= NN) return;
    int lane = threadIdx.x;
    int s = g_rs[node], d = g_deg[node];
    float acc[8] = {0.f, 0.f, 0.f, 0.f, 0.f, 0.f, 0.f, 0.f};
    for (int e = 0; e < d; e++) {
        int sn = g_csrc[s + e];
        uint4 v = *(const uint4*)(g_h + (size_t)sn * CH + lane * 8);
        float2 f0 = unpackh2(v.x), f1 = unpackh2(v.y);
        float2 f2 = unpackh2(v.z), f3 = unpackh2(v.w);
        acc[0] += f0.x; acc[1] += f0.y; acc[2] += f1.x; acc[3] += f1.y;
        acc[4] += f2.x; acc[5] += f2.y; acc[6] += f3.x; acc[7] += f3.y;
    }
    uint4 z = *(const uint4*)(g_h0 + (size_t)node * CH + lane * 8);
    float2 z0 = unpackh2(z.x), z1 = unpackh2(z.y);
    float2 z2 = unpackh2(z.z), z3 = unpackh2(z.w);
    float o[8];
    o[0] = 0.9f * acc[0] + 0.1f * z0.x;  o[1] = 0.9f * acc[1] + 0.1f * z0.y;
    o[2] = 0.9f * acc[2] + 0.1f * z1.x;  o[3] = 0.9f * acc[3] + 0.1f * z1.y;
    o[4] = 0.9f * acc[4] + 0.1f * z2.x;  o[5] = 0.9f * acc[5] + 0.1f * z2.y;
    o[6] = 0.9f * acc[6] + 0.1f * z3.x;  o[7] = 0.9f * acc[7] + 0.1f * z3.y;
    uint4 w;
    w.x = packh2(o[0], o[1]);  w.y = packh2(o[2], o[3]);
    w.z = packh2(o[4], o[5]);  w.w = packh2(o[6], o[7]);
    *(uint4*)(g_x + (size_t)node * CH + lane * 8) = w;
}

// ---------------- shared GEMM geometry ----------------
// 256 threads (8 warps), CTA 128M x 128N, warp grid 4m x 2n, warp tile 32x64.
#define GSTR 80            // smem fp16 row stride bytes (32 fp16 + pad)
#define GPLANE 10240       // 128*80

// ---------------- lin GEMM (cp.async fp32 A staging + smem convert) --------
// blockIdx.z = view (0: x0 -> cols 0..127, 1: x1 -> cols 128..255)
// A rows clamped to NN-1 (stores guarded), so all tiles use unpredicated cp.
#define A32STR 144         // fp32 staging row stride bytes
#define A32PLANE 18432     // 128*144
#define GSTAGE (A32PLANE + 2 * GPLANE)   // 38912
#define GSM_TOTAL (2 * GSTAGE)           // 77824

__global__ void __launch_bounds__(256, 2)
k_gemm2(const float* __restrict__ A0, const float* __restrict__ A1,
        const __half* __restrict__ BLw, const float* __restrict__ lin_b,
        __half* __restrict__ C, __half* __restrict__ C2, int M) {
    extern __shared__ __align__(16) char smem[];
    const uint32_t sb = smem_u32(smem);
    const int tid = threadIdx.x;
    const int wid = tid >> 5, lane = tid & 31;
    const int wm = wid >> 1, wn = wid & 1;
    const int m0 = blockIdx.y * 128;
    const int v = blockIdx.z;
    const float* A = v ? A1 : A0;
    const __half* Bw = BLw + v * 32768;
    const float* bias = lin_b + v * 128;
    const int ccol0 = v * 128;

    float acc[2][8][4];
    #pragma unroll
    for (int mt = 0; mt < 2; mt++)
        #pragma unroll
        for (int nt = 0; nt < 8; nt++)
            #pragma unroll
            for (int i = 0; i < 4; i++) acc[mt][nt][i] = 0.f;

    auto load_chunk = [&](int c, int st) {
        const int k0 = c * 32;
        const uint32_t base = sb + st * GSTAGE;
        #pragma unroll
        for (int i = 0; i < 4; i++) {
            int idx = tid + i * 256;           // 0..1023
            int row = idx >> 3, seg = idx & 7;
            int grow = m0 + row;
            if (grow > NN - 1) grow = NN - 1;  // clamp: loads in-bounds, stores guarded
            uint32_t dst = base + row * A32STR + seg * 16;
            CP16(dst, A + (size_t)grow * CH + k0 + seg * 4);
        }
        #pragma unroll
        for (int i = 0; i < 2; i++) {
            int idx = tid + i * 256;
            int row = idx >> 2, seg = idx & 3;
            uint32_t dst = base + A32PLANE + GPLANE + row * GSTR + seg * 16;
            CP16(dst, Bw + (size_t)row * CH + k0 + seg * 8);
        }
        CP_COMMIT();
    };
    const int arow = tid >> 1, acolh = (tid & 1) * 16;
    auto convertA = [&](int st) {
        const char* s32 = smem + st * GSTAGE + (uint32_t)arow * A32STR + acolh * 4;
        float4 a0 = *(const float4*)(s32 + 0);
        float4 a1 = *(const float4*)(s32 + 16);
        float4 a2 = *(const float4*)(s32 + 32);
        float4 a3 = *(const float4*)(s32 + 48);
        uint32_t d = (uint32_t)arow * GSTR + acolh * 2 + st * GSTAGE + A32PLANE;
        uint4 o0, o1;
        o0.x = packh2(a0.x, a0.y);  o0.y = packh2(a0.z, a0.w);
        o0.z = packh2(a1.x, a1.y);  o0.w = packh2(a1.z, a1.w);
        o1.x = packh2(a2.x, a2.y);  o1.y = packh2(a2.z, a2.w);
        o1.z = packh2(a3.x, a3.y);  o1.w = packh2(a3.z, a3.w);
        *(uint4*)(smem + d)      = o0;
        *(uint4*)(smem + d + 16) = o1;
    };

    load_chunk(0, 0);

    for (int c = 0; c < 8; c++) {
        const int st = c & 1;
        if (c + 1 < 8) load_chunk(c + 1, st ^ 1);
        if (c + 1 < 8) { CP_WAIT(1); } else { CP_WAIT(0); }
        __syncthreads();
        convertA(st);
        __syncthreads();

        const uint32_t base16 = sb + st * GSTAGE + A32PLANE;
        #pragma unroll
        for (int ks = 0; ks < 2; ks++) {
            const int akoff = ks * 32 + (lane >> 4) * 16;
            uint32_t a[2][4];
            const int ar = wm * 32 + (lane & 15);
            #pragma unroll
            for (int mt = 0; mt < 2; mt++)
                ldsm_x4(a[mt], base16 + (uint32_t)(ar + mt * 16) * GSTR + akoff);
            #pragma unroll
            for (int ntp = 0; ntp < 4; ntp++) {
                const int brow = wn * 64 + ntp * 16 + (lane & 15);
                uint32_t bw[4];
                ldsm_x4(bw, base16 + GPLANE + (uint32_t)brow * GSTR + akoff);
                #pragma unroll
                for (int mt = 0; mt < 2; mt++) {
                    mma16816h(acc[mt][2 * ntp],     a[mt], bw[0], bw[2]);
                    mma16816h(acc[mt][2 * ntp + 1], a[mt], bw[1], bw[3]);
                }
            }
        }
        __syncthreads();
    }

    // epilogue: bias + relu + fp16 store to both h0 and h
    #pragma unroll
    for (int mt = 0; mt < 2; mt++) {
        #pragma unroll
        for (int nt = 0; nt < 8; nt++) {
            int colL = wn * 64 + nt * 8 + (lane & 3) * 2;
            float2 bv = *(const float2*)(bias + colL);
            int colg = ccol0 + colL;
            #pragma unroll
            for (int half = 0; half < 2; half++) {
                int row = m0 + wm * 32 + mt * 16 + (lane >> 2) + half * 8;
                if (row >= M) continue;
                float vx = fmaxf(acc[mt][nt][half * 2 + 0] + bv.x, 0.f);
                float vy = fmaxf(acc[mt][nt][half * 2 + 1] + bv.y, 0.f);
                uint32_t pv = packh2(vx, vy);
                *(uint32_t*)(C + (size_t)row * CH + colg) = pv;
                *(uint32_t*)(C2 + (size_t)row * CH + colg) = pv;
            }
        }
    }
}

// ---------------- layer GEMM (fp16 A, 1-pass): C = relu(A @ Bw^T) ----------
#define G1STAGE 20480      // 2 planes (A, B)
#define G1SM_TOTAL 40960   // 2 stages

__global__ void __launch_bounds__(256, 2)
k_gemm1(const __half* __restrict__ A, const __half* __restrict__ Bw,
        __half* __restrict__ C, int M) {
    extern __shared__ __align__(16) char smem[];
    const uint32_t sb = smem_u32(smem);
    const int tid = threadIdx.x;
    const int wid = tid >> 5, lane = tid & 31;
    const int wm = wid >> 1, wn = wid & 1;
    const int m0 = blockIdx.y * 128;
    const int n0 = blockIdx.x * 128;

    float acc[2][8][4];
    #pragma unroll
    for (int mt = 0; mt < 2; mt++)
        #pragma unroll
        for (int nt = 0; nt < 8; nt++)
            #pragma unroll
            for (int i = 0; i < 4; i++) acc[mt][nt][i] = 0.f;

    auto load_chunk = [&](int c, int st) {
        const int k0 = c * 32;
        const uint32_t base = sb + st * G1STAGE;
        #pragma unroll
        for (int i = 0; i < 2; i++) {
            int idx = tid + i * 256;
            int row = idx >> 2, seg = idx & 3;
            uint32_t dst = base + row * GSTR + seg * 16;
            CP16(dst,          A  + (size_t)(m0 + row) * CH + k0 + seg * 8);
            CP16(dst + GPLANE, Bw + (size_t)(n0 + row) * CH + k0 + seg * 8);
        }
        CP_COMMIT();
    };

    load_chunk(0, 0);

    for (int c = 0; c < 8; c++) {
        if (c + 1 < 8) load_chunk(c + 1, (c + 1) & 1);
        if (c + 1 < 8) { CP_WAIT(1); } else { CP_WAIT(0); }
        __syncthreads();

        const uint32_t base = sb + (c & 1) * G1STAGE;
        #pragma unroll
        for (int ks = 0; ks < 2; ks++) {
            const int akoff = ks * 32 + (lane >> 4) * 16;
            uint32_t a[2][4];
            const int ar = wm * 32 + (lane & 15);
            #pragma unroll
            for (int mt = 0; mt < 2; mt++)
                ldsm_x4(a[mt], base + (uint32_t)(ar + mt * 16) * GSTR + akoff);
            #pragma unroll
            for (int ntp = 0; ntp < 4; ntp++) {
                const int brow = wn * 64 + ntp * 16 + (lane & 15);
                uint32_t bw[4];
                ldsm_x4(bw, base + GPLANE + (uint32_t)brow * GSTR + akoff);
                #pragma unroll
                for (int mt = 0; mt < 2; mt++) {
                    mma16816h(acc[mt][2 * ntp],     a[mt], bw[0], bw[2]);
                    mma16816h(acc[mt][2 * ntp + 1], a[mt], bw[1], bw[3]);
                }
            }
        }
        __syncthreads();
    }

    #pragma unroll
    for (int mt = 0; mt < 2; mt++) {
        #pragma unroll
        for (int nt = 0; nt < 8; nt++) {
            int colg = n0 + wn * 64 + nt * 8 + (lane & 3) * 2;
            #pragma unroll
            for (int half = 0; half < 2; half++) {
                int row = m0 + wm * 32 + mt * 16 + (lane >> 2) + half * 8;
                if (row >= M) continue;
                float vx = fmaxf(acc[mt][nt][half * 2 + 0], 0.f);
                float vy = fmaxf(acc[mt][nt][half * 2 + 1], 0.f);
                *(uint32_t*)(C + (size_t)row * CH + colg) = packh2(vx, vy);
            }
        }
    }
}

// ---------------- final projection: out = h @ out_w + out_b  [N,40] ------
// 128 rows per block, one row per thread pair.
__global__ void __launch_bounds__(256)
k_out(const __half* __restrict__ H, const float* __restrict__ Wo,
      const float* __restrict__ bo, float* __restrict__ O) {
    __shared__ float As[128][33];
    __shared__ float Ws[32][40];
    const int tid = threadIdx.x;
    const int m0 = blockIdx.x * 128;
    const int rg = tid >> 1;
    const int cg = tid & 1;

    float acc[20];
    #pragma unroll
    for (int j = 0; j < 20; j++) acc[j] = 0.f;

    for (int kt = 0; kt < CH; kt += 32) {
        #pragma unroll
        for (int i = 0; i < 8; i++) {
            int idx = tid + i * 256;            // 0..2047 half2 slots
            int r = idx >> 4, kh = (idx & 15) * 2;
            float2 f = make_float2(0.f, 0.f);
            int row = m0 + r;
            if (row < NN) {
                uint32_t u = *(const uint32_t*)(H + (size_t)row * CH + kt + kh);
                f = unpackh2(u);
            }
            As[r][kh + 0] = f.x;
            As[r][kh + 1] = f.y;
        }
        for (int i = tid; i < 32 * NCLS; i += 256)
            Ws[i / NCLS][i % NCLS] = Wo[(size_t)(kt + i / NCLS) * NCLS + (i % NCLS)];
        __syncthreads();
        #pragma unroll
        for (int k = 0; k < 32; k++) {
            float a0 = As[rg][k];
            #pragma unroll
            for (int j = 0; j < 20; j++)
                acc[j] = fmaf(a0, Ws[k][cg * 20 + j], acc[j]);
        }
        __syncthreads();
    }
    int row = m0 + rg;
    if (row < NN) {
        #pragma unroll
        for (int j = 0; j < 20; j++) {
            int col = cg * 20 + j;
            O[(size_t)row * NCLS + col] = acc[j] + bo[col];
        }
    }
}

// ---------------- launch ----------------
extern "C" void kernel_launch(void* const* d_in, const int* in_sizes, int n_in,
                              void* d_out, int out_size) {
    const float* x0    = (const float*)d_in[0];
    const float* x1    = (const float*)d_in[1];
    const int*   ei    = (const int*)d_in[2];
    const float* lin_w = (const float*)d_in[3];
    const float* lin_b = (const float*)d_in[4];
    const float* gcn_w = (const float*)d_in[5];
    const float* out_w = (const float*)d_in[6];
    const float* out_b = (const float*)d_in[7];
    float* out = (float*)d_out;

    const int* e_src = ei;
    const int* e_dst = ei + EE;

    __half *p_h0, *p_h, *p_x;
    __half *p_Bw, *p_BLw;
    cudaGetSymbolAddress((void**)&p_h0,  g_h0);
    cudaGetSymbolAddress((void**)&p_h,   g_h);
    cudaGetSymbolAddress((void**)&p_x,   g_x);
    cudaGetSymbolAddress((void**)&p_Bw,  g_Bw);
    cudaGetSymbolAddress((void**)&p_BLw, g_BLw);

    cudaFuncSetAttribute(k_gemm2, cudaFuncAttributeMaxDynamicSharedMemorySize, GSM_TOTAL);
    cudaFuncSetAttribute(k_gemm1, cudaFuncAttributeMaxDynamicSharedMemorySize, G1SM_TOTAL);

    const int mtiles = PADN / 128;   // 782

    // ---- launch order: index 3 (profiled) = merged lin GEMM ----
    k_prep_lin<<<(2 * 128 * 256 + 255) / 256, 256>>>(lin_w);           // 0
    k_prep_gcn<<<(LL * 256 * 256 + 255) / 256, 256>>>(gcn_w);          // 1
    k_zero_deg<<<(NN + 255) / 256, 256>>>();                           // 2
    k_gemm2<<<dim3(1, mtiles, 2), 256, GSM_TOTAL>>>(x0, x1, p_BLw,
                                                    lin_b, p_h0, p_h, NN);  // 3 <- profiled

    k_hist<<<(EE + 255) / 256, 256>>>(e_dst);
    k_scan1<<<SCAN_NB, SCAN_BS>>>();
    k_scan2<<<1, 32>>>();
    k_scan3<<<(NN + 255) / 256, 256>>>();
    k_scatter<<<(EE + 255) / 256, 256>>>(e_src, e_dst);

    // 8 GCNII layers: agg + single-pass GEMM
    for (int l = 0; l < LL; l++) {
        k_agg<<<(NN + 7) / 8, dim3(32, 8)>>>();
        k_gemm1<<<dim3(2, mtiles), 256, G1SM_TOTAL>>>(p_x,
                                                      p_Bw + (size_t)l * 65536,
                                                      p_h, NN);
    }

    // output projection
    k_out<<<(PADN + 127) / 128, 256>>>(p_h, out_w, out_b, out);
}

// round 17
// speedup vs baseline: 1.0203x; 1.0203x over previous
#include <cuda_runtime.h>
#include <cuda_fp16.h>
#include <math.h>
#include <stdint.h>

#define NN 100000
#define PADN 100096   // 782 * 128
#define EE 300000
#define CH 256
#define LL 8
#define NCLS 40
#define SCAN_BS 1024
#define SCAN_NB 98   // ceil(100000/1024)

// ---------------- helpers ----------------
__device__ __forceinline__ uint32_t smem_u32(const void* p) {
    uint32_t a;
    asm("{ .reg .u64 t; cvta.to.shared.u64 t, %1; cvt.u32.u64 %0, t; }" : "=r"(a) : "l"(p));
    return a;
}
__device__ __forceinline__ void ldsm_x4(uint32_t* r, uint32_t addr) {
    asm volatile("ldmatrix.sync.aligned.m8n8.x4.shared.b16 {%0,%1,%2,%3}, [%4];"
                 : "=r"(r[0]), "=r"(r[1]), "=r"(r[2]), "=r"(r[3]) : "r"(addr));
}
__device__ __forceinline__ void mma16816h(float* d, const uint32_t* a, uint32_t b0, uint32_t b1) {
    asm volatile(
        "mma.sync.aligned.m16n8k16.row.col.f32.f16.f16.f32 "
        "{%0,%1,%2,%3}, {%4,%5,%6,%7}, {%8,%9}, {%0,%1,%2,%3};"
        : "+f"(d[0]), "+f"(d[1]), "+f"(d[2]), "+f"(d[3])
        : "r"(a[0]), "r"(a[1]), "r"(a[2]), "r"(a[3]), "r"(b0), "r"(b1));
}
#define CP16(dst, src) \
    asm volatile("cp.async.cg.shared.global [%0], [%1], 16;" :: "r"(dst), "l"(src))
#define CP_COMMIT() asm volatile("cp.async.commit_group;" ::: "memory")
#define CP_WAIT(n)  asm volatile("cp.async.wait_group %0;" :: "n"(n) : "memory")

__device__ __forceinline__ uint32_t packh2(float a, float b) {
    __half2 h = __floats2half2_rn(a, b);
    return *(uint32_t*)&h;
}
__device__ __forceinline__ float2 unpackh2(uint32_t u) {
    return __half22float2(*(__half2*)&u);
}

// ---------------- device scratch ----------------
__device__ __half g_h0[(size_t)PADN * CH];          // fp16 h0
__device__ __half g_h [(size_t)PADN * CH];          // fp16 h
__device__ __half g_x [(size_t)PADN * CH];          // fp16 x plane (zero-padded tail)
__device__ __half g_Bw [(size_t)LL * 256 * 256];    // gcn eff weights [l][n][k], fp16
__device__ __half g_BLw[(size_t)2 * 128 * 256];     // lin weights [v][n][k], fp16
__device__ int   g_deg[NN];
__device__ int   g_rs [NN];
__device__ int   g_cur[NN];
__device__ int   g_incl[NN];
__device__ int   g_bsum[SCAN_NB];
__device__ int   g_boff[SCAN_NB];
__device__ int   g_csrc[EE];

// ---------------- weight prep ----------------
__global__ void k_prep_gcn(const float* __restrict__ gcn_w) {
    int idx = blockIdx.x * blockDim.x + threadIdx.x;
    if (idx >= LL * 256 * 256) return;
    int l = idx >> 16;
    int n = (idx >> 8) & 255;
    int k = idx & 255;
    float beta = logf(0.5f / (float)(l + 1) + 1.0f);
    float w = gcn_w[l * 65536 + k * 256 + n];
    float eff = beta * w + ((n == k) ? (1.0f - beta) : 0.0f);
    g_Bw[idx] = __float2half_rn(eff);
}
__global__ void k_prep_lin(const float* __restrict__ lin_w) {
    int idx = blockIdx.x * blockDim.x + threadIdx.x;
    if (idx >= 2 * 128 * 256) return;
    int v = idx >> 15;
    int n = (idx >> 8) & 127;
    int k = idx & 255;
    g_BLw[idx] = __float2half_rn(lin_w[v * 32768 + k * 128 + n]);
}

// ---------------- CSR build ----------------
__global__ void k_zero_deg() {
    int i = blockIdx.x * blockDim.x + threadIdx.x;
    if (i < NN) g_deg[i] = 0;
}
__global__ void k_hist(const int* __restrict__ dst) {
    int e = blockIdx.x * blockDim.x + threadIdx.x;
    if (e < EE) atomicAdd(&g_deg[dst[e]], 1);
}
__global__ void k_scan1() {
    __shared__ int sm[SCAN_BS];
    int tid = threadIdx.x;
    int i = blockIdx.x * SCAN_BS + tid;
    int v = (i < NN) ? g_deg[i] : 0;
    sm[tid] = v;
    __syncthreads();
    for (int off = 1; off < SCAN_BS; off <<= 1) {
        int t = (tid >= off) ? sm[tid - off] : 0;
        __syncthreads();
        sm[tid] += t;
        __syncthreads();
    }
    if (i < NN) g_incl[i] = sm[tid];
    if (tid == SCAN_BS - 1) g_bsum[blockIdx.x] = sm[tid];
}
__global__ void k_scan2() {
    if (threadIdx.x == 0) {
        int s = 0;
        for (int b = 0; b < SCAN_NB; b++) { g_boff[b] = s; s += g_bsum[b]; }
    }
}
__global__ void k_scan3() {
    int i = blockIdx.x * blockDim.x + threadIdx.x;
    if (i >= NN) return;
    int rs = g_boff[i >> 10] + g_incl[i] - g_deg[i];
    g_rs[i] = rs;
    g_cur[i] = rs;
}
__global__ void k_scatter(const int* __restrict__ src, const int* __restrict__ dst) {
    int e = blockIdx.x * blockDim.x + threadIdx.x;
    if (e >= EE) return;
    int p = atomicAdd(&g_cur[dst[e]], 1);
    g_csrc[p] = src[e];
}

// ---- aggregation: x = fp16(0.9*sum Hin[src] + 0.1*h0) ----
// Hin = g_h0 for layer 0 (h == h0 then), g_h afterwards.
__global__ void k_agg(const __half* __restrict__ Hin) {
    int node = blockIdx.x * blockDim.y + threadIdx.y;
    if (node >= NN) return;
    int lane = threadIdx.x;
    int s = g_rs[node], d = g_deg[node];
    float acc[8] = {0.f, 0.f, 0.f, 0.f, 0.f, 0.f, 0.f, 0.f};
    for (int e = 0; e < d; e++) {
        int sn = g_csrc[s + e];
        uint4 v = *(const uint4*)(Hin + (size_t)sn * CH + lane * 8);
        float2 f0 = unpackh2(v.x), f1 = unpackh2(v.y);
        float2 f2 = unpackh2(v.z), f3 = unpackh2(v.w);
        acc[0] += f0.x; acc[1] += f0.y; acc[2] += f1.x; acc[3] += f1.y;
        acc[4] += f2.x; acc[5] += f2.y; acc[6] += f3.x; acc[7] += f3.y;
    }
    uint4 z = *(const uint4*)(g_h0 + (size_t)node * CH + lane * 8);
    float2 z0 = unpackh2(z.x), z1 = unpackh2(z.y);
    float2 z2 = unpackh2(z.z), z3 = unpackh2(z.w);
    float o[8];
    o[0] = 0.9f * acc[0] + 0.1f * z0.x;  o[1] = 0.9f * acc[1] + 0.1f * z0.y;
    o[2] = 0.9f * acc[2] + 0.1f * z1.x;  o[3] = 0.9f * acc[3] + 0.1f * z1.y;
    o[4] = 0.9f * acc[4] + 0.1f * z2.x;  o[5] = 0.9f * acc[5] + 0.1f * z2.y;
    o[6] = 0.9f * acc[6] + 0.1f * z3.x;  o[7] = 0.9f * acc[7] + 0.1f * z3.y;
    uint4 w;
    w.x = packh2(o[0], o[1]);  w.y = packh2(o[2], o[3]);
    w.z = packh2(o[4], o[5]);  w.w = packh2(o[6], o[7]);
    *(uint4*)(g_x + (size_t)node * CH + lane * 8) = w;
}

// ---------------- shared GEMM geometry ----------------
// 256 threads (8 warps), CTA 128M x 128N, warp grid 4m x 2n, warp tile 32x64.
#define GSTR 80            // smem fp16 row stride bytes (32 fp16 + pad)
#define GPLANE 10240       // 128*80

// ---------------- lin GEMM (fp32 A register load + convert, fp16 B) --------
// blockIdx.z = view (0: x0 -> cols 0..127, 1: x1 -> cols 128..255)
// writes h0 ONLY (layer 0 agg reads h0 directly).
#define GSTAGE 20480       // 2 planes (A, B)
#define GSM_TOTAL 40960    // 2 stages

__global__ void __launch_bounds__(256, 2)
k_gemm2(const float* __restrict__ A0, const float* __restrict__ A1,
        const __half* __restrict__ BLw, const float* __restrict__ lin_b,
        __half* __restrict__ C, int M) {
    extern __shared__ __align__(16) char smem[];
    const uint32_t sb = smem_u32(smem);
    const int tid = threadIdx.x;
    const int wid = tid >> 5, lane = tid & 31;
    const int wm = wid >> 1, wn = wid & 1;
    const int m0 = blockIdx.y * 128;
    const int v = blockIdx.z;
    const float* A = v ? A1 : A0;
    const __half* Bw = BLw + v * 32768;
    const float* bias = lin_b + v * 128;
    const int ccol0 = v * 128;

    float acc[2][8][4];
    #pragma unroll
    for (int mt = 0; mt < 2; mt++)
        #pragma unroll
        for (int nt = 0; nt < 8; nt++)
            #pragma unroll
            for (int i = 0; i < 4; i++) acc[mt][nt][i] = 0.f;

    const int arow = tid >> 1, acolh = (tid & 1) * 16;
    auto loadB = [&](int c, int st) {
        const int k0 = c * 32;
        const uint32_t base = sb + st * GSTAGE;
        #pragma unroll
        for (int i = 0; i < 2; i++) {
            int idx = tid + i * 256;
            int row = idx >> 2, seg = idx & 3;
            uint32_t dst = base + row * GSTR + seg * 16;
            CP16(dst + GPLANE, Bw + (size_t)row * CH + k0 + seg * 8);
        }
        CP_COMMIT();
    };
    auto loadA_regs = [&](int c, float4* av) {
        const float* src = A + (size_t)(m0 + arow) * CH + c * 32 + acolh;
        if (m0 + arow < M) {
            av[0] = *(const float4*)(src + 0);
            av[1] = *(const float4*)(src + 4);
            av[2] = *(const float4*)(src + 8);
            av[3] = *(const float4*)(src + 12);
        } else {
            av[0] = av[1] = av[2] = av[3] = make_float4(0.f, 0.f, 0.f, 0.f);
        }
    };
    auto storeA = [&](int st, const float4* av) {
        uint32_t dst = (uint32_t)arow * GSTR + acolh * 2 + st * GSTAGE;
        uint4 o0, o1;
        o0.x = packh2(av[0].x, av[0].y);  o0.y = packh2(av[0].z, av[0].w);
        o0.z = packh2(av[1].x, av[1].y);  o0.w = packh2(av[1].z, av[1].w);
        o1.x = packh2(av[2].x, av[2].y);  o1.y = packh2(av[2].z, av[2].w);
        o1.z = packh2(av[3].x, av[3].y);  o1.w = packh2(av[3].z, av[3].w);
        *(uint4*)(smem + dst)      = o0;
        *(uint4*)(smem + dst + 16) = o1;
    };

    // prologue
    {
        float4 av[4];
        loadA_regs(0, av);
        storeA(0, av);
        loadB(0, 0);
    }

    float4 avn[4];
    for (int c = 0; c < 8; c++) {
        const int st = c & 1;
        if (c + 1 < 8) {
            loadA_regs(c + 1, avn);
            loadB(c + 1, st ^ 1);
        }
        if (c + 1 < 8) { CP_WAIT(1); } else { CP_WAIT(0); }
        __syncthreads();

        const uint32_t base = sb + st * GSTAGE;
        #pragma unroll
        for (int ks = 0; ks < 2; ks++) {
            const int akoff = ks * 32 + (lane >> 4) * 16;
            uint32_t a[2][4];
            const int ar = wm * 32 + (lane & 15);
            #pragma unroll
            for (int mt = 0; mt < 2; mt++)
                ldsm_x4(a[mt], base + (uint32_t)(ar + mt * 16) * GSTR + akoff);
            #pragma unroll
            for (int ntp = 0; ntp < 4; ntp++) {
                const int brow = wn * 64 + ntp * 16 + (lane & 15);
                uint32_t bw[4];
                ldsm_x4(bw, base + GPLANE + (uint32_t)brow * GSTR + akoff);
                #pragma unroll
                for (int mt = 0; mt < 2; mt++) {
                    mma16816h(acc[mt][2 * ntp],     a[mt], bw[0], bw[2]);
                    mma16816h(acc[mt][2 * ntp + 1], a[mt], bw[1], bw[3]);
                }
            }
        }
        if (c + 1 < 8) {
            __syncthreads();
            storeA(st ^ 1, avn);
        }
    }

    // epilogue: bias + relu + fp16 store to h0 only
    #pragma unroll
    for (int mt = 0; mt < 2; mt++) {
        #pragma unroll
        for (int nt = 0; nt < 8; nt++) {
            int colL = wn * 64 + nt * 8 + (lane & 3) * 2;
            float2 bv = *(const float2*)(bias + colL);
            int colg = ccol0 + colL;
            #pragma unroll
            for (int half = 0; half < 2; half++) {
                int row = m0 + wm * 32 + mt * 16 + (lane >> 2) + half * 8;
                if (row >= M) continue;
                float vx = fmaxf(acc[mt][nt][half * 2 + 0] + bv.x, 0.f);
                float vy = fmaxf(acc[mt][nt][half * 2 + 1] + bv.y, 0.f);
                *(uint32_t*)(C + (size_t)row * CH + colg) = packh2(vx, vy);
            }
        }
    }
}

// ---------------- layer GEMM (fp16 A, 1-pass): C = relu(A @ Bw^T) ----------
#define G1STAGE 20480      // 2 planes (A, B)
#define G1SM_TOTAL 40960   // 2 stages

__global__ void __launch_bounds__(256, 2)
k_gemm1(const __half* __restrict__ A, const __half* __restrict__ Bw,
        __half* __restrict__ C, int M) {
    extern __shared__ __align__(16) char smem[];
    const uint32_t sb = smem_u32(smem);
    const int tid = threadIdx.x;
    const int wid = tid >> 5, lane = tid & 31;
    const int wm = wid >> 1, wn = wid & 1;
    const int m0 = blockIdx.y * 128;
    const int n0 = blockIdx.x * 128;

    float acc[2][8][4];
    #pragma unroll
    for (int mt = 0; mt < 2; mt++)
        #pragma unroll
        for (int nt = 0; nt < 8; nt++)
            #pragma unroll
            for (int i = 0; i < 4; i++) acc[mt][nt][i] = 0.f;

    auto load_chunk = [&](int c, int st) {
        const int k0 = c * 32;
        const uint32_t base = sb + st * G1STAGE;
        #pragma unroll
        for (int i = 0; i < 2; i++) {
            int idx = tid + i * 256;
            int row = idx >> 2, seg = idx & 3;
            uint32_t dst = base + row * GSTR + seg * 16;
            CP16(dst,          A  + (size_t)(m0 + row) * CH + k0 + seg * 8);
            CP16(dst + GPLANE, Bw + (size_t)(n0 + row) * CH + k0 + seg * 8);
        }
        CP_COMMIT();
    };

    load_chunk(0, 0);

    for (int c = 0; c < 8; c++) {
        if (c + 1 < 8) load_chunk(c + 1, (c + 1) & 1);
        if (c + 1 < 8) { CP_WAIT(1); } else { CP_WAIT(0); }
        __syncthreads();

        const uint32_t base = sb + (c & 1) * G1STAGE;
        #pragma unroll
        for (int ks = 0; ks < 2; ks++) {
            const int akoff = ks * 32 + (lane >> 4) * 16;
            uint32_t a[2][4];
            const int ar = wm * 32 + (lane & 15);
            #pragma unroll
            for (int mt = 0; mt < 2; mt++)
                ldsm_x4(a[mt], base + (uint32_t)(ar + mt * 16) * GSTR + akoff);
            #pragma unroll
            for (int ntp = 0; ntp < 4; ntp++) {
                const int brow = wn * 64 + ntp * 16 + (lane & 15);
                uint32_t bw[4];
                ldsm_x4(bw, base + GPLANE + (uint32_t)brow * GSTR + akoff);
                #pragma unroll
                for (int mt = 0; mt < 2; mt++) {
                    mma16816h(acc[mt][2 * ntp],     a[mt], bw[0], bw[2]);
                    mma16816h(acc[mt][2 * ntp + 1], a[mt], bw[1], bw[3]);
                }
            }
        }
        __syncthreads();
    }

    #pragma unroll
    for (int mt = 0; mt < 2; mt++) {
        #pragma unroll
        for (int nt = 0; nt < 8; nt++) {
            int colg = n0 + wn * 64 + nt * 8 + (lane & 3) * 2;
            #pragma unroll
            for (int half = 0; half < 2; half++) {
                int row = m0 + wm * 32 + mt * 16 + (lane >> 2) + half * 8;
                if (row >= M) continue;
                float vx = fmaxf(acc[mt][nt][half * 2 + 0], 0.f);
                float vy = fmaxf(acc[mt][nt][half * 2 + 1], 0.f);
                *(uint32_t*)(C + (size_t)row * CH + colg) = packh2(vx, vy);
            }
        }
    }
}

// ---------------- final projection: out = h @ out_w + out_b  [N,40] ------
// 128 rows per block, one row per thread pair.
__global__ void __launch_bounds__(256)
k_out(const __half* __restrict__ H, const float* __restrict__ Wo,
      const float* __restrict__ bo, float* __restrict__ O) {
    __shared__ float As[128][33];
    __shared__ float Ws[32][40];
    const int tid = threadIdx.x;
    const int m0 = blockIdx.x * 128;
    const int rg = tid >> 1;
    const int cg = tid & 1;

    float acc[20];
    #pragma unroll
    for (int j = 0; j < 20; j++) acc[j] = 0.f;

    for (int kt = 0; kt < CH; kt += 32) {
        #pragma unroll
        for (int i = 0; i < 8; i++) {
            int idx = tid + i * 256;            // 0..2047 half2 slots
            int r = idx >> 4, kh = (idx & 15) * 2;
            float2 f = make_float2(0.f, 0.f);
            int row = m0 + r;
            if (row < NN) {
                uint32_t u = *(const uint32_t*)(H + (size_t)row * CH + kt + kh);
                f = unpackh2(u);
            }
            As[r][kh + 0] = f.x;
            As[r][kh + 1] = f.y;
        }
        for (int i = tid; i < 32 * NCLS; i += 256)
            Ws[i / NCLS][i % NCLS] = Wo[(size_t)(kt + i / NCLS) * NCLS + (i % NCLS)];
        __syncthreads();
        #pragma unroll
        for (int k = 0; k < 32; k++) {
            float a0 = As[rg][k];
            #pragma unroll
            for (int j = 0; j < 20; j++)
                acc[j] = fmaf(a0, Ws[k][cg * 20 + j], acc[j]);
        }
        __syncthreads();
    }
    int row = m0 + rg;
    if (row < NN) {
        #pragma unroll
        for (int j = 0; j < 20; j++) {
            int col = cg * 20 + j;
            O[(size_t)row * NCLS + col] = acc[j] + bo[col];
        }
    }
}

// ---------------- launch ----------------
extern "C" void kernel_launch(void* const* d_in, const int* in_sizes, int n_in,
                              void* d_out, int out_size) {
    const float* x0    = (const float*)d_in[0];
    const float* x1    = (const float*)d_in[1];
    const int*   ei    = (const int*)d_in[2];
    const float* lin_w = (const float*)d_in[3];
    const float* lin_b = (const float*)d_in[4];
    const float* gcn_w = (const float*)d_in[5];
    const float* out_w = (const float*)d_in[6];
    const float* out_b = (const float*)d_in[7];
    float* out = (float*)d_out;

    const int* e_src = ei;
    const int* e_dst = ei + EE;

    __half *p_h0, *p_h, *p_x;
    __half *p_Bw, *p_BLw;
    cudaGetSymbolAddress((void**)&p_h0,  g_h0);
    cudaGetSymbolAddress((void**)&p_h,   g_h);
    cudaGetSymbolAddress((void**)&p_x,   g_x);
    cudaGetSymbolAddress((void**)&p_Bw,  g_Bw);
    cudaGetSymbolAddress((void**)&p_BLw, g_BLw);

    cudaFuncSetAttribute(k_gemm2, cudaFuncAttributeMaxDynamicSharedMemorySize, GSM_TOTAL);
    cudaFuncSetAttribute(k_gemm1, cudaFuncAttributeMaxDynamicSharedMemorySize, G1SM_TOTAL);

    const int mtiles = PADN / 128;   // 782

    // ---- launch order: index 3 (profiled) = merged lin GEMM ----
    k_prep_lin<<<(2 * 128 * 256 + 255) / 256, 256>>>(lin_w);           // 0
    k_prep_gcn<<<(LL * 256 * 256 + 255) / 256, 256>>>(gcn_w);          // 1
    k_zero_deg<<<(NN + 255) / 256, 256>>>();                           // 2
    k_gemm2<<<dim3(1, mtiles, 2), 256, GSM_TOTAL>>>(x0, x1, p_BLw,
                                                    lin_b, p_h0, NN);  // 3 <- profiled

    k_hist<<<(EE + 255) / 256, 256>>>(e_dst);
    k_scan1<<<SCAN_NB, SCAN_BS>>>();
    k_scan2<<<1, 32>>>();
    k_scan3<<<(NN + 255) / 256, 256>>>();
    k_scatter<<<(EE + 255) / 256, 256>>>(e_src, e_dst);

    // 8 GCNII layers: agg (layer 0 reads h0) + single-pass GEMM
    for (int l = 0; l < LL; l++) {
        k_agg<<<(NN + 7) / 8, dim3(32, 8)>>>(l == 0 ? p_h0 : p_h);
        k_gemm1<<<dim3(2, mtiles), 256, G1SM_TOTAL>>>(p_x,
                                                      p_Bw + (size_t)l * 65536,
                                                      p_h, NN);
    }

    // output projection
    k_out<<<(PADN + 127) / 128, 256>>>(p_h, out_w, out_b, out);
}